// round 13
// baseline (speedup 1.0000x reference)
#include <cuda_runtime.h>
#include <cuda_fp16.h>
#include <cstdint>
#include <cstring>

// Problem constants (fixed shapes):
//   B=128, T=2048, F_IN=32, R=256, H=256, F_OUT=32, future_n=64
//   total tokens N = 128 * (2048+64) = 270336
#define NTOTAL 270336
#define TTOT   2112
#define TIN    2048
#define NTILE  1056          // 256-token tiles (16 warps x 16 tokens)
#define GRID   148

// Fused-weight fp16 hi/lo images (gmem, written by prep):
//   Wg: [768 gate-cols (i:0-255, g:256-511, o:512-767)][32 k]
//   dW: [32 o][256 k]
__device__ unsigned short g_WgH[768 * 32];
__device__ unsigned short g_WgL[768 * 32];
__device__ unsigned short g_dWH[32 * 256];
__device__ unsigned short g_dWL[32 * 256];
__device__ float g_bias[768];

// ---- SMEM layout (bytes). Wg rows padded to 40 halfs (80B, conflict-free
// for ldmatrix); dW stored k-chunked [4][32 o][64k pad 72]. ----
#define WG_H     0            // 768*40*2 = 61440
#define WG_L     61440
#define DW_H     122880       // 128*72*2 = 18432
#define DW_L     141312
#define BIAS_OFF 159744       // 768 f32
#define DECB_OFF 162816       // 32 f32
#define SMEM_TOTAL 162944

__device__ __forceinline__ uint32_t smem_u32(const void* p) {
    uint32_t a;
    asm("{ .reg .u64 t; cvta.to.shared.u64 t, %1; cvt.u32.u64 %0, t; }"
        : "=r"(a) : "l"(p));
    return a;
}
__device__ __forceinline__ void ldsm4(uint32_t& r0, uint32_t& r1,
                                      uint32_t& r2, uint32_t& r3, uint32_t a) {
    asm volatile("ldmatrix.sync.aligned.m8n8.x4.shared.b16 {%0,%1,%2,%3}, [%4];"
                 : "=r"(r0), "=r"(r1), "=r"(r2), "=r"(r3) : "r"(a));
}
__device__ __forceinline__ void mma16816(float* d,
                                         uint32_t a0, uint32_t a1,
                                         uint32_t a2, uint32_t a3,
                                         uint32_t b0, uint32_t b1) {
    asm volatile(
        "mma.sync.aligned.m16n8k16.row.col.f32.f16.f16.f32 "
        "{%0,%1,%2,%3}, {%4,%5,%6,%7}, {%8,%9}, {%0,%1,%2,%3};"
        : "+f"(d[0]), "+f"(d[1]), "+f"(d[2]), "+f"(d[3])
        : "r"(a0), "r"(a1), "r"(a2), "r"(a3), "r"(b0), "r"(b1));
}
// MUFU.TANH activations (validated rel_err ~5e-6)
__device__ __forceinline__ float tanh_a(float v) {
    float r; asm("tanh.approx.f32 %0, %1;" : "=f"(r) : "f"(v)); return r;
}
__device__ __forceinline__ float sig_a(float v) {
    return fmaf(0.5f, tanh_a(0.5f * v), 0.5f);
}
__device__ __forceinline__ float actf(float iv, float gv, float ov) {
    float cc = sig_a(iv) * tanh_a(gv);
    return sig_a(ov) * tanh_a(cc);
}
// fp16 hi/lo split of a float pair -> packed f16x2 regs (lo-half = first arg)
__device__ __forceinline__ void hsplit(float a, float b,
                                       uint32_t& hi, uint32_t& lo) {
    __half2 h = __floats2half2_rn(a, b);
    float2 bk = __half22float2(h);
    __half2 l = __floats2half2_rn(a - bk.x, b - bk.y);
    memcpy(&hi, &h, 4);
    memcpy(&lo, &l, 4);
}

// ---------------------------------------------------------------------------
// K1: fold encoder into LSTM input weights -> fp16 hi/lo images.
//   bid <  768 : fused M row (one k per lane)
//   768..791   : fused biases
//   792..823   : dec_W row (o = bid-792)
// ---------------------------------------------------------------------------
__global__ void prep_kernel(const float* __restrict__ Wih,
                            const float* __restrict__ encW,
                            const float* __restrict__ encb,
                            const float* __restrict__ bih,
                            const float* __restrict__ bhh,
                            const float* __restrict__ decW) {
    __shared__ float wr_s[256];
    int bid = blockIdx.x, lane = threadIdx.x;
    if (bid < 768) {
        int p  = bid >> 8;
        int hj = bid & 255;
        int row = hj + (p == 0 ? 0 : (p == 1 ? 512 : 768));
        const float* wr = Wih + row * 256;
        #pragma unroll
        for (int i = 0; i < 8; i++) wr_s[lane + 32 * i] = wr[lane + 32 * i];
        __syncwarp();
        float s = 0.0f;
        #pragma unroll 8
        for (int r = 0; r < 256; r++) s += wr_s[r] * encW[r * 32 + lane];
        __half hi = __float2half_rn(s);
        __half lo = __float2half_rn(s - __half2float(hi));
        int idx = bid * 32 + lane;          // col*32 + k
        g_WgH[idx] = *(unsigned short*)&hi;
        g_WgL[idx] = *(unsigned short*)&lo;
    } else if (bid < 792) {
        int q = (bid - 768) * 32 + lane;    // 0..767
        int p  = q >> 8;
        int hj = q & 255;
        int row = hj + (p == 0 ? 0 : (p == 1 ? 512 : 768));
        const float* wr = Wih + row * 256;
        float s = 0.0f;
        #pragma unroll 8
        for (int r = 0; r < 256; r++) s += wr[r] * encb[r];
        g_bias[p * 256 + hj] = s + bih[row] + bhh[row];
    } else {
        int o = bid - 792;                  // 0..31
        #pragma unroll
        for (int i = 0; i < 8; i++) {
            int k = lane + 32 * i;
            float v = decW[o * 256 + k];
            __half hi = __float2half_rn(v);
            __half lo = __float2half_rn(v - __half2float(hi));
            g_dWH[o * 256 + k] = *(unsigned short*)&hi;
            g_dWL[o * 256 + k] = *(unsigned short*)&lo;
        }
    }
}

// ---------------------------------------------------------------------------
// K2: persistent fused kernel. 148 CTAs x 512 threads (16 warps), 1 CTA/SM.
// Each warp owns 16 tokens of a 256-token tile, end-to-end, no tile barriers.
// Inner loops are restructured so consecutive HMMA never hit the same
// accumulator within distance 4 (4 acc groups rotate: both n-tiles of the
// chunk interleaved) — kills the D-RAW serialization seen at R10 (tensor 59%).
// 512T (128-reg cap) gives ptxas headroom for B-frags + pipelining, unlike
// the reg-starved 768T config (80 regs = persistent state alone).
// ---------------------------------------------------------------------------
__global__ __launch_bounds__(512)
void fused_kernel(const float* __restrict__ x,
                  const float* __restrict__ decb,
                  float* __restrict__ out) {
    extern __shared__ char smem[];
    int tid = threadIdx.x, wid = tid >> 5, lane = tid & 31;

    // ---- stage split weights into padded smem ----
    {
        unsigned short* wgH = (unsigned short*)(smem + WG_H);
        unsigned short* wgL = (unsigned short*)(smem + WG_L);
        for (int i = tid; i < 24576; i += 512) {
            int col = i >> 5, k = i & 31;
            wgH[col * 40 + k] = g_WgH[i];
            wgL[col * 40 + k] = g_WgL[i];
        }
        unsigned short* dwH = (unsigned short*)(smem + DW_H);
        unsigned short* dwL = (unsigned short*)(smem + DW_L);
        for (int i = tid; i < 8192; i += 512) {
            int o = i >> 8, k = i & 255;
            int row = (k >> 6) * 32 + o, ck = k & 63;
            dwH[row * 72 + ck] = g_dWH[i];
            dwL[row * 72 + ck] = g_dWL[i];
        }
        float* bs = (float*)(smem + BIAS_OFF);
        for (int i = tid; i < 768; i += 512) bs[i] = g_bias[i];
        if (tid < 32) ((float*)(smem + DECB_OFF))[tid] = decb[tid];
    }
    __syncthreads();

    uint32_t sb = smem_u32(smem);
    const float* bias_s = (const float*)(smem + BIAS_OFF);
    const float* decb_s = (const float*)(smem + DECB_OFF);

    // ldmatrix lane geometry: j = lane/8 selects (ntile, k-half)
    int jrow = ((lane >> 4) & 1) * 8 + (lane & 7);
    int jcol = ((lane >> 3) & 1) * 8;
    int qr = lane >> 2, qc = (lane & 3) * 2;
    int m0 = wid * 16;

    for (int tile = blockIdx.x; tile < NTILE; tile += GRID) {
        int n0t  = tile * 256;
        int tok0 = n0t + m0 + qr;
        // clamped x row pointers (future steps reuse last input step)
        int b0i = tok0 / TTOT, t0 = tok0 - b0i * TTOT;
        if (t0 > TIN - 1) t0 = TIN - 1;
        int tok1 = tok0 + 8;
        int b1i = tok1 / TTOT, t1 = tok1 - b1i * TTOT;
        if (t1 > TIN - 1) t1 = TIN - 1;
        const float* xr0 = x + ((size_t)b0i * TIN + t0) * 32 + qc;
        const float* xr1 = x + ((size_t)b1i * TIN + t1) * 32 + qc;

        // A fragments for X: [kstep][a0..a3], fp16 hi + lo
        uint32_t axh[2][4], axl[2][4];
        #pragma unroll
        for (int ks = 0; ks < 2; ks++) {
            float2 f0 = *(const float2*)(xr0 + ks * 16);
            float2 f1 = *(const float2*)(xr1 + ks * 16);
            float2 f2 = *(const float2*)(xr0 + ks * 16 + 8);
            float2 f3 = *(const float2*)(xr1 + ks * 16 + 8);
            hsplit(f0.x, f0.y, axh[ks][0], axl[ks][0]);
            hsplit(f1.x, f1.y, axh[ks][1], axl[ks][1]);
            hsplit(f2.x, f2.y, axh[ks][2], axl[ks][2]);
            hsplit(f3.x, f3.y, axh[ks][3], axl[ks][3]);
        }

        float dacc[16];
        #pragma unroll
        for (int i = 0; i < 16; i++) dacc[i] = 0.0f;

        #pragma unroll 1
        for (int c = 0; c < 8; c++) {         // 32-hj chunks (2 n-tiles)
            float aI[16], aG[16], aO[16];
            #pragma unroll
            for (int i = 0; i < 16; i++) { aI[i] = 0.f; aG[i] = 0.f; aO[i] = 0.f; }

            #pragma unroll
            for (int g3 = 0; g3 < 3; g3++) {
                float* acc = (g3 == 0) ? aI : (g3 == 1 ? aG : aO);
                int colb = g3 * 256 + c * 32;
                #pragma unroll
                for (int ks = 0; ks < 2; ks++) {
                    // load B-hi for BOTH n-tiles, then rotate 4 accumulators
                    uint32_t adr0 = sb + WG_H +
                        (uint32_t)((colb + jrow) * 40 + ks * 16 + jcol) * 2;
                    uint32_t adr1 = sb + WG_H +
                        (uint32_t)((colb + 16 + jrow) * 40 + ks * 16 + jcol) * 2;
                    uint32_t h0, h1, h2, h3, h4, h5, h6, h7;
                    ldsm4(h0, h1, h2, h3, adr0);
                    ldsm4(h4, h5, h6, h7, adr1);
                    mma16816(acc + 0,  axh[ks][0], axh[ks][1], axh[ks][2], axh[ks][3], h0, h1);
                    mma16816(acc + 4,  axh[ks][0], axh[ks][1], axh[ks][2], axh[ks][3], h2, h3);
                    mma16816(acc + 8,  axh[ks][0], axh[ks][1], axh[ks][2], axh[ks][3], h4, h5);
                    mma16816(acc + 12, axh[ks][0], axh[ks][1], axh[ks][2], axh[ks][3], h6, h7);
                    mma16816(acc + 0,  axl[ks][0], axl[ks][1], axl[ks][2], axl[ks][3], h0, h1);
                    mma16816(acc + 4,  axl[ks][0], axl[ks][1], axl[ks][2], axl[ks][3], h2, h3);
                    mma16816(acc + 8,  axl[ks][0], axl[ks][1], axl[ks][2], axl[ks][3], h4, h5);
                    mma16816(acc + 12, axl[ks][0], axl[ks][1], axl[ks][2], axl[ks][3], h6, h7);
                    // B-lo for both n-tiles (x-hi term)
                    uint32_t l0, l1, l2, l3, l4, l5, l6, l7;
                    ldsm4(l0, l1, l2, l3, adr0 + (WG_L - WG_H));
                    ldsm4(l4, l5, l6, l7, adr1 + (WG_L - WG_H));
                    mma16816(acc + 0,  axh[ks][0], axh[ks][1], axh[ks][2], axh[ks][3], l0, l1);
                    mma16816(acc + 4,  axh[ks][0], axh[ks][1], axh[ks][2], axh[ks][3], l2, l3);
                    mma16816(acc + 8,  axh[ks][0], axh[ks][1], axh[ks][2], axh[ks][3], l4, l5);
                    mma16816(acc + 12, axh[ks][0], axh[ks][1], axh[ks][2], axh[ks][3], l6, l7);
                }
            }

            // activation -> h fragments (hi/lo), already in decoder-A layout
            uint32_t hh[8], hl[8];
            #pragma unroll
            for (int nt = 0; nt < 4; nt++) {
                int col = c * 32 + nt * 8 + qc;
                float2 bi = *(const float2*)&bias_s[col];
                float2 bg = *(const float2*)&bias_s[256 + col];
                float2 bo = *(const float2*)&bias_s[512 + col];
                int q = nt * 4;
                float h0 = actf(aI[q]     + bi.x, aG[q]     + bg.x, aO[q]     + bo.x);
                float h1 = actf(aI[q + 1] + bi.y, aG[q + 1] + bg.y, aO[q + 1] + bo.y);
                float h2 = actf(aI[q + 2] + bi.x, aG[q + 2] + bg.x, aO[q + 2] + bo.x);
                float h3 = actf(aI[q + 3] + bi.y, aG[q + 3] + bg.y, aO[q + 3] + bo.y);
                hsplit(h0, h1, hh[nt * 2],     hl[nt * 2]);
                hsplit(h2, h3, hh[nt * 2 + 1], hl[nt * 2 + 1]);
            }

            // decoder partial over this chunk's 32 k (h) values;
            // both o-tiles interleaved -> 4 rotating accumulators
            #pragma unroll
            for (int ks = 0; ks < 2; ks++) {
                int gk = c * 32 + ks * 16;             // global k
                int kc = gk >> 6, ck = gk & 63;
                uint32_t a0h = hh[4 * ks], a1h = hh[4 * ks + 1];
                uint32_t a2h = hh[4 * ks + 2], a3h = hh[4 * ks + 3];
                uint32_t a0l = hl[4 * ks], a1l = hl[4 * ks + 1];
                uint32_t a2l = hl[4 * ks + 2], a3l = hl[4 * ks + 3];
                uint32_t adr0 = sb + DW_H +
                    (uint32_t)((kc * 32 + jrow) * 72 + ck + jcol) * 2;
                uint32_t adr1 = sb + DW_H +
                    (uint32_t)((kc * 32 + 16 + jrow) * 72 + ck + jcol) * 2;
                uint32_t h0, h1, h2, h3, h4, h5, h6, h7;
                ldsm4(h0, h1, h2, h3, adr0);
                ldsm4(h4, h5, h6, h7, adr1);
                mma16816(dacc + 0,  a0h, a1h, a2h, a3h, h0, h1);
                mma16816(dacc + 4,  a0h, a1h, a2h, a3h, h2, h3);
                mma16816(dacc + 8,  a0h, a1h, a2h, a3h, h4, h5);
                mma16816(dacc + 12, a0h, a1h, a2h, a3h, h6, h7);
                mma16816(dacc + 0,  a0l, a1l, a2l, a3l, h0, h1);
                mma16816(dacc + 4,  a0l, a1l, a2l, a3l, h2, h3);
                mma16816(dacc + 8,  a0l, a1l, a2l, a3l, h4, h5);
                mma16816(dacc + 12, a0l, a1l, a2l, a3l, h6, h7);
                uint32_t l0, l1, l2, l3, l4, l5, l6, l7;
                ldsm4(l0, l1, l2, l3, adr0 + (DW_L - DW_H));
                ldsm4(l4, l5, l6, l7, adr1 + (DW_L - DW_H));
                mma16816(dacc + 0,  a0h, a1h, a2h, a3h, l0, l1);
                mma16816(dacc + 4,  a0h, a1h, a2h, a3h, l2, l3);
                mma16816(dacc + 8,  a0h, a1h, a2h, a3h, l4, l5);
                mma16816(dacc + 12, a0h, a1h, a2h, a3h, l6, l7);
            }
        }

        // epilogue: out = dacc + dec_b
        // dacc layout: [otp*8 + pair*4 + q] where otp o-base = otp*16,
        // pair o-base = pair*8  (dacc+0: o 0-7, +4: o 8-15, +8: o 16-23, +12: o 24-31)
        #pragma unroll
        for (int ot = 0; ot < 4; ot++) {
            int col = ot * 8 + qc;
            float2 db = *(const float2*)&decb_s[col];
            float2 r0, r1;
            r0.x = dacc[ot * 4]     + db.x;  r0.y = dacc[ot * 4 + 1] + db.y;
            r1.x = dacc[ot * 4 + 2] + db.x;  r1.y = dacc[ot * 4 + 3] + db.y;
            *(float2*)&out[(size_t)tok0 * 32 + col]       = r0;
            *(float2*)&out[(size_t)(tok0 + 8) * 32 + col] = r1;
        }
    }
}

// ---------------------------------------------------------------------------
// Inputs (metadata order): input_seq, enc_W, enc_b, W_ih, W_hh, b_ih, b_hh,
//                          dec_W, dec_b, future_n
// W_hh is dead (state never updates from zeros); future_n fixed at 64.
// ---------------------------------------------------------------------------
extern "C" void kernel_launch(void* const* d_in, const int* in_sizes, int n_in,
                              void* d_out, int out_size) {
    (void)in_sizes; (void)n_in; (void)out_size;
    const float* input = (const float*)d_in[0];
    const float* encW  = (const float*)d_in[1];
    const float* encb  = (const float*)d_in[2];
    const float* Wih   = (const float*)d_in[3];
    const float* bih   = (const float*)d_in[5];
    const float* bhh   = (const float*)d_in[6];
    const float* decW  = (const float*)d_in[7];
    const float* decb  = (const float*)d_in[8];
    float* out = (float*)d_out;

    cudaFuncSetAttribute(fused_kernel,
                         cudaFuncAttributeMaxDynamicSharedMemorySize, SMEM_TOTAL);

    prep_kernel<<<824, 32>>>(Wih, encW, encb, bih, bhh, decW);
    fused_kernel<<<GRID, 512, SMEM_TOTAL>>>(input, decb, out);
}

// round 14
// speedup vs baseline: 1.3372x; 1.3372x over previous
#include <cuda_runtime.h>
#include <cuda_fp16.h>
#include <cstdint>
#include <cstring>

// Problem constants (fixed shapes):
//   B=128, T=2048, F_IN=32, R=256, H=256, F_OUT=32, future_n=64
//   total tokens N = 128 * (2048+64) = 270336
#define NTOTAL 270336
#define TTOT   2112
#define TIN    2048
#define NTILE  704           // 384-token tiles (24 warps x 16 tokens)
#define GRID   148

// Fused-weight fp16 images (hi only — 2-term split drops the W-lo term):
//   Wg: [768 gate-cols (i:0-255, g:256-511, o:512-767)][32 k]
//   dW: [32 o][256 k]
__device__ unsigned short g_WgH[768 * 32];
__device__ unsigned short g_dWH[32 * 256];
__device__ float g_bias[768];

// ---- SMEM layout (bytes). Wg rows padded to 40 halfs (80B, conflict-free
// for ldmatrix); dW stored k-chunked [4][32 o][64k pad 72]. ----
#define WG_H     0            // 768*40*2 = 61440
#define DW_H     61440        // 128*72*2 = 18432
#define BIAS_OFF 79872        // 768 f32
#define DECB_OFF 82944        // 32 f32
#define SMEM_TOTAL 83072

__device__ __forceinline__ uint32_t smem_u32(const void* p) {
    uint32_t a;
    asm("{ .reg .u64 t; cvta.to.shared.u64 t, %1; cvt.u32.u64 %0, t; }"
        : "=r"(a) : "l"(p));
    return a;
}
__device__ __forceinline__ void ldsm4(uint32_t& r0, uint32_t& r1,
                                      uint32_t& r2, uint32_t& r3, uint32_t a) {
    asm volatile("ldmatrix.sync.aligned.m8n8.x4.shared.b16 {%0,%1,%2,%3}, [%4];"
                 : "=r"(r0), "=r"(r1), "=r"(r2), "=r"(r3) : "r"(a));
}
__device__ __forceinline__ void mma16816(float* d,
                                         uint32_t a0, uint32_t a1,
                                         uint32_t a2, uint32_t a3,
                                         uint32_t b0, uint32_t b1) {
    asm volatile(
        "mma.sync.aligned.m16n8k16.row.col.f32.f16.f16.f32 "
        "{%0,%1,%2,%3}, {%4,%5,%6,%7}, {%8,%9}, {%0,%1,%2,%3};"
        : "+f"(d[0]), "+f"(d[1]), "+f"(d[2]), "+f"(d[3])
        : "r"(a0), "r"(a1), "r"(a2), "r"(a3), "r"(b0), "r"(b1));
}
// MUFU.TANH activations
__device__ __forceinline__ float tanh_a(float v) {
    float r; asm("tanh.approx.f32 %0, %1;" : "=f"(r) : "f"(v)); return r;
}
__device__ __forceinline__ float sig_a(float v) {
    return fmaf(0.5f, tanh_a(0.5f * v), 0.5f);
}
__device__ __forceinline__ float actf(float iv, float gv, float ov) {
    float cc = sig_a(iv) * tanh_a(gv);
    return sig_a(ov) * tanh_a(cc);
}
// fp16 hi/lo split of a float pair -> packed f16x2 regs (lo-half = first arg)
__device__ __forceinline__ void hsplit(float a, float b,
                                       uint32_t& hi, uint32_t& lo) {
    __half2 h = __floats2half2_rn(a, b);
    float2 bk = __half22float2(h);
    __half2 l = __floats2half2_rn(a - bk.x, b - bk.y);
    memcpy(&hi, &h, 4);
    memcpy(&lo, &l, 4);
}

// ---------------------------------------------------------------------------
// K1: fold encoder into LSTM input weights -> fp16 hi images.
//   bid <  768 : fused M row (one k per lane)
//   768..791   : fused biases
//   792..823   : dec_W row (o = bid-792)
// ---------------------------------------------------------------------------
__global__ void prep_kernel(const float* __restrict__ Wih,
                            const float* __restrict__ encW,
                            const float* __restrict__ encb,
                            const float* __restrict__ bih,
                            const float* __restrict__ bhh,
                            const float* __restrict__ decW) {
    __shared__ float wr_s[256];
    int bid = blockIdx.x, lane = threadIdx.x;
    if (bid < 768) {
        int p  = bid >> 8;
        int hj = bid & 255;
        int row = hj + (p == 0 ? 0 : (p == 1 ? 512 : 768));
        const float* wr = Wih + row * 256;
        #pragma unroll
        for (int i = 0; i < 8; i++) wr_s[lane + 32 * i] = wr[lane + 32 * i];
        __syncwarp();
        float s = 0.0f;
        #pragma unroll 8
        for (int r = 0; r < 256; r++) s += wr_s[r] * encW[r * 32 + lane];
        __half hi = __float2half_rn(s);
        g_WgH[bid * 32 + lane] = *(unsigned short*)&hi;
    } else if (bid < 792) {
        int q = (bid - 768) * 32 + lane;    // 0..767
        int p  = q >> 8;
        int hj = q & 255;
        int row = hj + (p == 0 ? 0 : (p == 1 ? 512 : 768));
        const float* wr = Wih + row * 256;
        float s = 0.0f;
        #pragma unroll 8
        for (int r = 0; r < 256; r++) s += wr[r] * encb[r];
        g_bias[p * 256 + hj] = s + bih[row] + bhh[row];
    } else {
        int o = bid - 792;                  // 0..31
        #pragma unroll
        for (int i = 0; i < 8; i++) {
            int k = lane + 32 * i;
            __half hi = __float2half_rn(decW[o * 256 + k]);
            g_dWH[o * 256 + k] = *(unsigned short*)&hi;
        }
    }
}

// ---------------------------------------------------------------------------
// K2: persistent fused kernel. 148 CTAs x 768 threads (24 warps), 1 CTA/SM.
// 24 warps is the RF-imposed occupancy ceiling (persistent accs = 64 regs).
// 2-term split: (xh + xl) @ Wh  — the W-lo term is dropped (-33% MMA/ldsm).
// Each warp owns 16 tokens of a 384-token tile, end-to-end, no tile barriers.
// ---------------------------------------------------------------------------
__global__ __launch_bounds__(768)
void fused_kernel(const float* __restrict__ x,
                  const float* __restrict__ decb,
                  float* __restrict__ out) {
    extern __shared__ char smem[];
    int tid = threadIdx.x, wid = tid >> 5, lane = tid & 31;

    // ---- stage weights into padded smem ----
    {
        unsigned short* wgH = (unsigned short*)(smem + WG_H);
        for (int i = tid; i < 24576; i += 768) {
            int col = i >> 5, k = i & 31;
            wgH[col * 40 + k] = g_WgH[i];
        }
        unsigned short* dwH = (unsigned short*)(smem + DW_H);
        for (int i = tid; i < 8192; i += 768) {
            int o = i >> 8, k = i & 255;
            int row = (k >> 6) * 32 + o, ck = k & 63;
            dwH[row * 72 + ck] = g_dWH[i];
        }
        float* bs = (float*)(smem + BIAS_OFF);
        for (int i = tid; i < 768; i += 768) bs[i] = g_bias[i];
        if (tid < 32) ((float*)(smem + DECB_OFF))[tid] = decb[tid];
    }
    __syncthreads();

    uint32_t sb = smem_u32(smem);
    const float* bias_s = (const float*)(smem + BIAS_OFF);
    const float* decb_s = (const float*)(smem + DECB_OFF);

    // ldmatrix lane geometry: j = lane/8 selects (ntile, k-half)
    int jrow = ((lane >> 4) & 1) * 8 + (lane & 7);
    int jcol = ((lane >> 3) & 1) * 8;
    int qr = lane >> 2, qc = (lane & 3) * 2;
    int m0 = wid * 16;

    for (int tile = blockIdx.x; tile < NTILE; tile += GRID) {
        int n0t  = tile * 384;
        int tok0 = n0t + m0 + qr;
        // clamped x row pointers (future steps reuse last input step)
        int b0i = tok0 / TTOT, t0 = tok0 - b0i * TTOT;
        if (t0 > TIN - 1) t0 = TIN - 1;
        int tok1 = tok0 + 8;
        int b1i = tok1 / TTOT, t1 = tok1 - b1i * TTOT;
        if (t1 > TIN - 1) t1 = TIN - 1;
        const float* xr0 = x + ((size_t)b0i * TIN + t0) * 32 + qc;
        const float* xr1 = x + ((size_t)b1i * TIN + t1) * 32 + qc;

        // A fragments for X: [kstep][a0..a3], fp16 hi + lo
        uint32_t axh[2][4], axl[2][4];
        #pragma unroll
        for (int ks = 0; ks < 2; ks++) {
            float2 f0 = *(const float2*)(xr0 + ks * 16);
            float2 f1 = *(const float2*)(xr1 + ks * 16);
            float2 f2 = *(const float2*)(xr0 + ks * 16 + 8);
            float2 f3 = *(const float2*)(xr1 + ks * 16 + 8);
            hsplit(f0.x, f0.y, axh[ks][0], axl[ks][0]);
            hsplit(f1.x, f1.y, axh[ks][1], axl[ks][1]);
            hsplit(f2.x, f2.y, axh[ks][2], axl[ks][2]);
            hsplit(f3.x, f3.y, axh[ks][3], axl[ks][3]);
        }

        float dacc[16];
        #pragma unroll
        for (int i = 0; i < 16; i++) dacc[i] = 0.0f;

        #pragma unroll 1
        for (int c = 0; c < 8; c++) {         // 32-hj chunks
            float aI[16], aG[16], aO[16];
            #pragma unroll
            for (int i = 0; i < 16; i++) { aI[i] = 0.f; aG[i] = 0.f; aO[i] = 0.f; }

            #pragma unroll
            for (int g3 = 0; g3 < 3; g3++) {
                float* acc = (g3 == 0) ? aI : (g3 == 1 ? aG : aO);
                int colb = g3 * 256 + c * 32;
                #pragma unroll
                for (int ntp = 0; ntp < 2; ntp++) {
                    int nw = colb + ntp * 16;
                    #pragma unroll
                    for (int ks = 0; ks < 2; ks++) {
                        uint32_t adr = sb + WG_H +
                            (uint32_t)((nw + jrow) * 40 + ks * 16 + jcol) * 2;
                        uint32_t bh0, bh1, bh2, bh3;
                        ldsm4(bh0, bh1, bh2, bh3, adr);
                        float* A0 = acc + ntp * 8;
                        float* A1 = acc + ntp * 8 + 4;
                        mma16816(A0, axh[ks][0], axh[ks][1], axh[ks][2], axh[ks][3], bh0, bh1);
                        mma16816(A1, axh[ks][0], axh[ks][1], axh[ks][2], axh[ks][3], bh2, bh3);
                        mma16816(A0, axl[ks][0], axl[ks][1], axl[ks][2], axl[ks][3], bh0, bh1);
                        mma16816(A1, axl[ks][0], axl[ks][1], axl[ks][2], axl[ks][3], bh2, bh3);
                    }
                }
            }

            // activation -> h fragments (hi/lo), already in decoder-A layout
            uint32_t hh[8], hl[8];
            #pragma unroll
            for (int nt = 0; nt < 4; nt++) {
                int col = c * 32 + nt * 8 + qc;
                float2 bi = *(const float2*)&bias_s[col];
                float2 bg = *(const float2*)&bias_s[256 + col];
                float2 bo = *(const float2*)&bias_s[512 + col];
                int q = nt * 4;
                float h0 = actf(aI[q]     + bi.x, aG[q]     + bg.x, aO[q]     + bo.x);
                float h1 = actf(aI[q + 1] + bi.y, aG[q + 1] + bg.y, aO[q + 1] + bo.y);
                float h2 = actf(aI[q + 2] + bi.x, aG[q + 2] + bg.x, aO[q + 2] + bo.x);
                float h3 = actf(aI[q + 3] + bi.y, aG[q + 3] + bg.y, aO[q + 3] + bo.y);
                hsplit(h0, h1, hh[nt * 2],     hl[nt * 2]);
                hsplit(h2, h3, hh[nt * 2 + 1], hl[nt * 2 + 1]);
            }

            // decoder partial over this chunk's 32 k (h) values
            #pragma unroll
            for (int ks = 0; ks < 2; ks++) {
                int gk = c * 32 + ks * 16;             // global k
                int kc = gk >> 6, ck = gk & 63;
                uint32_t a0h = hh[4 * ks], a1h = hh[4 * ks + 1];
                uint32_t a2h = hh[4 * ks + 2], a3h = hh[4 * ks + 3];
                uint32_t a0l = hl[4 * ks], a1l = hl[4 * ks + 1];
                uint32_t a2l = hl[4 * ks + 2], a3l = hl[4 * ks + 3];
                #pragma unroll
                for (int otp = 0; otp < 2; otp++) {
                    uint32_t adr = sb + DW_H +
                        (uint32_t)((kc * 32 + otp * 16 + jrow) * 72 + ck + jcol) * 2;
                    uint32_t bh0, bh1, bh2, bh3;
                    ldsm4(bh0, bh1, bh2, bh3, adr);
                    float* D0 = dacc + otp * 8;
                    float* D1 = dacc + otp * 8 + 4;
                    mma16816(D0, a0h, a1h, a2h, a3h, bh0, bh1);
                    mma16816(D1, a0h, a1h, a2h, a3h, bh2, bh3);
                    mma16816(D0, a0l, a1l, a2l, a3l, bh0, bh1);
                    mma16816(D1, a0l, a1l, a2l, a3l, bh2, bh3);
                }
            }
        }

        // epilogue: out = dacc + dec_b
        #pragma unroll
        for (int ot = 0; ot < 4; ot++) {
            int col = ot * 8 + qc;
            float2 db = *(const float2*)&decb_s[col];
            float2 r0, r1;
            r0.x = dacc[ot * 4]     + db.x;  r0.y = dacc[ot * 4 + 1] + db.y;
            r1.x = dacc[ot * 4 + 2] + db.x;  r1.y = dacc[ot * 4 + 3] + db.y;
            *(float2*)&out[(size_t)tok0 * 32 + col]       = r0;
            *(float2*)&out[(size_t)(tok0 + 8) * 32 + col] = r1;
        }
    }
}

// ---------------------------------------------------------------------------
// Inputs (metadata order): input_seq, enc_W, enc_b, W_ih, W_hh, b_ih, b_hh,
//                          dec_W, dec_b, future_n
// W_hh is dead (state never updates from zeros); future_n fixed at 64.
// ---------------------------------------------------------------------------
extern "C" void kernel_launch(void* const* d_in, const int* in_sizes, int n_in,
                              void* d_out, int out_size) {
    (void)in_sizes; (void)n_in; (void)out_size;
    const float* input = (const float*)d_in[0];
    const float* encW  = (const float*)d_in[1];
    const float* encb  = (const float*)d_in[2];
    const float* Wih   = (const float*)d_in[3];
    const float* bih   = (const float*)d_in[5];
    const float* bhh   = (const float*)d_in[6];
    const float* decW  = (const float*)d_in[7];
    const float* decb  = (const float*)d_in[8];
    float* out = (float*)d_out;

    cudaFuncSetAttribute(fused_kernel,
                         cudaFuncAttributeMaxDynamicSharedMemorySize, SMEM_TOTAL);

    prep_kernel<<<824, 32>>>(Wih, encW, encb, bih, bhh, decW);
    fused_kernel<<<GRID, 768, SMEM_TOTAL>>>(input, decb, out);
}

// round 15
// speedup vs baseline: 1.5054x; 1.1258x over previous
#include <cuda_runtime.h>
#include <cuda_fp16.h>
#include <cstdint>
#include <cstring>

// Problem constants (fixed shapes):
//   B=128, T=2048, F_IN=32, R=256, H=256, F_OUT=32, future_n=64
//   total tokens N = 128 * (2048+64) = 270336
#define NTOTAL 270336
#define TTOT   2112
#define TIN    2048
#define NTILE  704           // 384-token tiles (24 warps x 16 tokens)
#define GRID   148

// Fused-weight fp16 images (hi only):
//   Wg: [768 gate-cols (i:0-255, g:256-511, o:512-767)][32 k]
//   dW: [32 o][256 k]
__device__ unsigned short g_WgH[768 * 32];
__device__ unsigned short g_dWH[32 * 256];
__device__ float g_bias[768];

// ---- SMEM layout (bytes). Wg rows padded to 40 halfs (80B, conflict-free
// for ldmatrix); dW stored k-chunked [4][32 o][64k pad 72]. ----
#define WG_H     0            // 768*40*2 = 61440
#define DW_H     61440        // 128*72*2 = 18432
#define BIAS_OFF 79872        // 768 f32
#define DECB_OFF 82944        // 32 f32
#define SMEM_TOTAL 83072

__device__ __forceinline__ uint32_t smem_u32(const void* p) {
    uint32_t a;
    asm("{ .reg .u64 t; cvta.to.shared.u64 t, %1; cvt.u32.u64 %0, t; }"
        : "=r"(a) : "l"(p));
    return a;
}
__device__ __forceinline__ void ldsm4(uint32_t& r0, uint32_t& r1,
                                      uint32_t& r2, uint32_t& r3, uint32_t a) {
    asm volatile("ldmatrix.sync.aligned.m8n8.x4.shared.b16 {%0,%1,%2,%3}, [%4];"
                 : "=r"(r0), "=r"(r1), "=r"(r2), "=r"(r3) : "r"(a));
}
__device__ __forceinline__ void mma16816(float* d,
                                         uint32_t a0, uint32_t a1,
                                         uint32_t a2, uint32_t a3,
                                         uint32_t b0, uint32_t b1) {
    asm volatile(
        "mma.sync.aligned.m16n8k16.row.col.f32.f16.f16.f32 "
        "{%0,%1,%2,%3}, {%4,%5,%6,%7}, {%8,%9}, {%0,%1,%2,%3};"
        : "+f"(d[0]), "+f"(d[1]), "+f"(d[2]), "+f"(d[3])
        : "r"(a0), "r"(a1), "r"(a2), "r"(a3), "r"(b0), "r"(b1));
}
// MUFU.TANH activations
__device__ __forceinline__ float tanh_a(float v) {
    float r; asm("tanh.approx.f32 %0, %1;" : "=f"(r) : "f"(v)); return r;
}
__device__ __forceinline__ float sig_a(float v) {
    return fmaf(0.5f, tanh_a(0.5f * v), 0.5f);
}
__device__ __forceinline__ float actf(float iv, float gv, float ov) {
    float cc = sig_a(iv) * tanh_a(gv);
    return sig_a(ov) * tanh_a(cc);
}
// fp16 hi/lo split of a float pair -> packed f16x2 regs (lo-half = first arg)
__device__ __forceinline__ void hsplit(float a, float b,
                                       uint32_t& hi, uint32_t& lo) {
    __half2 h = __floats2half2_rn(a, b);
    float2 bk = __half22float2(h);
    __half2 l = __floats2half2_rn(a - bk.x, b - bk.y);
    memcpy(&hi, &h, 4);
    memcpy(&lo, &l, 4);
}

// ---------------------------------------------------------------------------
// K1: fold encoder into LSTM input weights -> fp16 hi images.
//   bid <  768 : fused M row (one k per lane)
//   768..791   : fused biases
//   792..823   : dec_W row (o = bid-792)
// ---------------------------------------------------------------------------
__global__ void prep_kernel(const float* __restrict__ Wih,
                            const float* __restrict__ encW,
                            const float* __restrict__ encb,
                            const float* __restrict__ bih,
                            const float* __restrict__ bhh,
                            const float* __restrict__ decW) {
    __shared__ float wr_s[256];
    int bid = blockIdx.x, lane = threadIdx.x;
    if (bid < 768) {
        int p  = bid >> 8;
        int hj = bid & 255;
        int row = hj + (p == 0 ? 0 : (p == 1 ? 512 : 768));
        const float* wr = Wih + row * 256;
        #pragma unroll
        for (int i = 0; i < 8; i++) wr_s[lane + 32 * i] = wr[lane + 32 * i];
        __syncwarp();
        float s = 0.0f;
        #pragma unroll 8
        for (int r = 0; r < 256; r++) s += wr_s[r] * encW[r * 32 + lane];
        __half hi = __float2half_rn(s);
        g_WgH[bid * 32 + lane] = *(unsigned short*)&hi;
    } else if (bid < 792) {
        int q = (bid - 768) * 32 + lane;    // 0..767
        int p  = q >> 8;
        int hj = q & 255;
        int row = hj + (p == 0 ? 0 : (p == 1 ? 512 : 768));
        const float* wr = Wih + row * 256;
        float s = 0.0f;
        #pragma unroll 8
        for (int r = 0; r < 256; r++) s += wr[r] * encb[r];
        g_bias[p * 256 + hj] = s + bih[row] + bhh[row];
    } else {
        int o = bid - 792;                  // 0..31
        #pragma unroll
        for (int i = 0; i < 8; i++) {
            int k = lane + 32 * i;
            __half hi = __float2half_rn(decW[o * 256 + k]);
            g_dWH[o * 256 + k] = *(unsigned short*)&hi;
        }
    }
}

// ---------------------------------------------------------------------------
// K2: persistent fused kernel. 148 CTAs x 768 threads (24 warps), 1 CTA/SM.
// 24 warps is the RF-imposed occupancy ceiling.
// Gates: 2-term split (xh + xl) @ Wh.  Decoder: 1-term hh @ dWh (h-lo
// dropped: -64 MMA, -32 ldsm, -hsplit fma per warp-tile; est +1.5e-4 err).
// Chunk loop unrolled x2 so ptxas can interleave chunk c+1 gates MMA into
// chunk c's MUFU-heavy activation region (phase-overlap attempt).
// ---------------------------------------------------------------------------
__global__ __launch_bounds__(768)
void fused_kernel(const float* __restrict__ x,
                  const float* __restrict__ decb,
                  float* __restrict__ out) {
    extern __shared__ char smem[];
    int tid = threadIdx.x, wid = tid >> 5, lane = tid & 31;

    // ---- stage weights into padded smem ----
    {
        unsigned short* wgH = (unsigned short*)(smem + WG_H);
        for (int i = tid; i < 24576; i += 768) {
            int col = i >> 5, k = i & 31;
            wgH[col * 40 + k] = g_WgH[i];
        }
        unsigned short* dwH = (unsigned short*)(smem + DW_H);
        for (int i = tid; i < 8192; i += 768) {
            int o = i >> 8, k = i & 255;
            int row = (k >> 6) * 32 + o, ck = k & 63;
            dwH[row * 72 + ck] = g_dWH[i];
        }
        float* bs = (float*)(smem + BIAS_OFF);
        for (int i = tid; i < 768; i += 768) bs[i] = g_bias[i];
        if (tid < 32) ((float*)(smem + DECB_OFF))[tid] = decb[tid];
    }
    __syncthreads();

    uint32_t sb = smem_u32(smem);
    const float* bias_s = (const float*)(smem + BIAS_OFF);
    const float* decb_s = (const float*)(smem + DECB_OFF);

    // ldmatrix lane geometry: j = lane/8 selects (ntile, k-half)
    int jrow = ((lane >> 4) & 1) * 8 + (lane & 7);
    int jcol = ((lane >> 3) & 1) * 8;
    int qr = lane >> 2, qc = (lane & 3) * 2;
    int m0 = wid * 16;

    for (int tile = blockIdx.x; tile < NTILE; tile += GRID) {
        int n0t  = tile * 384;
        int tok0 = n0t + m0 + qr;
        // clamped x row pointers (future steps reuse last input step)
        int b0i = tok0 / TTOT, t0 = tok0 - b0i * TTOT;
        if (t0 > TIN - 1) t0 = TIN - 1;
        int tok1 = tok0 + 8;
        int b1i = tok1 / TTOT, t1 = tok1 - b1i * TTOT;
        if (t1 > TIN - 1) t1 = TIN - 1;
        const float* xr0 = x + ((size_t)b0i * TIN + t0) * 32 + qc;
        const float* xr1 = x + ((size_t)b1i * TIN + t1) * 32 + qc;

        // A fragments for X: [kstep][a0..a3], fp16 hi + lo
        uint32_t axh[2][4], axl[2][4];
        #pragma unroll
        for (int ks = 0; ks < 2; ks++) {
            float2 f0 = *(const float2*)(xr0 + ks * 16);
            float2 f1 = *(const float2*)(xr1 + ks * 16);
            float2 f2 = *(const float2*)(xr0 + ks * 16 + 8);
            float2 f3 = *(const float2*)(xr1 + ks * 16 + 8);
            hsplit(f0.x, f0.y, axh[ks][0], axl[ks][0]);
            hsplit(f1.x, f1.y, axh[ks][1], axl[ks][1]);
            hsplit(f2.x, f2.y, axh[ks][2], axl[ks][2]);
            hsplit(f3.x, f3.y, axh[ks][3], axl[ks][3]);
        }

        float dacc[16];
        #pragma unroll
        for (int i = 0; i < 16; i++) dacc[i] = 0.0f;

        #pragma unroll 2
        for (int c = 0; c < 8; c++) {         // 32-hj chunks
            float aI[16], aG[16], aO[16];
            #pragma unroll
            for (int i = 0; i < 16; i++) { aI[i] = 0.f; aG[i] = 0.f; aO[i] = 0.f; }

            #pragma unroll
            for (int g3 = 0; g3 < 3; g3++) {
                float* acc = (g3 == 0) ? aI : (g3 == 1 ? aG : aO);
                int colb = g3 * 256 + c * 32;
                #pragma unroll
                for (int ntp = 0; ntp < 2; ntp++) {
                    int nw = colb + ntp * 16;
                    #pragma unroll
                    for (int ks = 0; ks < 2; ks++) {
                        uint32_t adr = sb + WG_H +
                            (uint32_t)((nw + jrow) * 40 + ks * 16 + jcol) * 2;
                        uint32_t bh0, bh1, bh2, bh3;
                        ldsm4(bh0, bh1, bh2, bh3, adr);
                        float* A0 = acc + ntp * 8;
                        float* A1 = acc + ntp * 8 + 4;
                        mma16816(A0, axh[ks][0], axh[ks][1], axh[ks][2], axh[ks][3], bh0, bh1);
                        mma16816(A1, axh[ks][0], axh[ks][1], axh[ks][2], axh[ks][3], bh2, bh3);
                        mma16816(A0, axl[ks][0], axl[ks][1], axl[ks][2], axl[ks][3], bh0, bh1);
                        mma16816(A1, axl[ks][0], axl[ks][1], axl[ks][2], axl[ks][3], bh2, bh3);
                    }
                }
            }

            // activation -> h fragments (hi only), already in decoder-A layout
            uint32_t hh[8];
            #pragma unroll
            for (int nt = 0; nt < 4; nt++) {
                int col = c * 32 + nt * 8 + qc;
                float2 bi = *(const float2*)&bias_s[col];
                float2 bg = *(const float2*)&bias_s[256 + col];
                float2 bo = *(const float2*)&bias_s[512 + col];
                int q = nt * 4;
                float h0 = actf(aI[q]     + bi.x, aG[q]     + bg.x, aO[q]     + bo.x);
                float h1 = actf(aI[q + 1] + bi.y, aG[q + 1] + bg.y, aO[q + 1] + bo.y);
                float h2 = actf(aI[q + 2] + bi.x, aG[q + 2] + bg.x, aO[q + 2] + bo.x);
                float h3 = actf(aI[q + 3] + bi.y, aG[q + 3] + bg.y, aO[q + 3] + bo.y);
                __half2 p0 = __floats2half2_rn(h0, h1);
                __half2 p1 = __floats2half2_rn(h2, h3);
                memcpy(&hh[nt * 2],     &p0, 4);
                memcpy(&hh[nt * 2 + 1], &p1, 4);
            }

            // decoder partial over this chunk's 32 k (h) values — hi term only
            #pragma unroll
            for (int ks = 0; ks < 2; ks++) {
                int gk = c * 32 + ks * 16;             // global k
                int kc = gk >> 6, ck = gk & 63;
                uint32_t a0h = hh[4 * ks], a1h = hh[4 * ks + 1];
                uint32_t a2h = hh[4 * ks + 2], a3h = hh[4 * ks + 3];
                #pragma unroll
                for (int otp = 0; otp < 2; otp++) {
                    uint32_t adr = sb + DW_H +
                        (uint32_t)((kc * 32 + otp * 16 + jrow) * 72 + ck + jcol) * 2;
                    uint32_t bh0, bh1, bh2, bh3;
                    ldsm4(bh0, bh1, bh2, bh3, adr);
                    float* D0 = dacc + otp * 8;
                    float* D1 = dacc + otp * 8 + 4;
                    mma16816(D0, a0h, a1h, a2h, a3h, bh0, bh1);
                    mma16816(D1, a0h, a1h, a2h, a3h, bh2, bh3);
                }
            }
        }

        // epilogue: out = dacc + dec_b
        #pragma unroll
        for (int ot = 0; ot < 4; ot++) {
            int col = ot * 8 + qc;
            float2 db = *(const float2*)&decb_s[col];
            float2 r0, r1;
            r0.x = dacc[ot * 4]     + db.x;  r0.y = dacc[ot * 4 + 1] + db.y;
            r1.x = dacc[ot * 4 + 2] + db.x;  r1.y = dacc[ot * 4 + 3] + db.y;
            *(float2*)&out[(size_t)tok0 * 32 + col]       = r0;
            *(float2*)&out[(size_t)(tok0 + 8) * 32 + col] = r1;
        }
    }
}

// ---------------------------------------------------------------------------
// Inputs (metadata order): input_seq, enc_W, enc_b, W_ih, W_hh, b_ih, b_hh,
//                          dec_W, dec_b, future_n
// W_hh is dead (state never updates from zeros); future_n fixed at 64.
// ---------------------------------------------------------------------------
extern "C" void kernel_launch(void* const* d_in, const int* in_sizes, int n_in,
                              void* d_out, int out_size) {
    (void)in_sizes; (void)n_in; (void)out_size;
    const float* input = (const float*)d_in[0];
    const float* encW  = (const float*)d_in[1];
    const float* encb  = (const float*)d_in[2];
    const float* Wih   = (const float*)d_in[3];
    const float* bih   = (const float*)d_in[5];
    const float* bhh   = (const float*)d_in[6];
    const float* decW  = (const float*)d_in[7];
    const float* decb  = (const float*)d_in[8];
    float* out = (float*)d_out;

    cudaFuncSetAttribute(fused_kernel,
                         cudaFuncAttributeMaxDynamicSharedMemorySize, SMEM_TOTAL);

    prep_kernel<<<824, 32>>>(Wih, encW, encb, bih, bhh, decW);
    fused_kernel<<<GRID, 768, SMEM_TOTAL>>>(input, decb, out);
}

// round 17
// speedup vs baseline: 1.7247x; 1.1457x over previous
#include <cuda_runtime.h>
#include <cuda_fp16.h>
#include <cstdint>
#include <cstring>

// Problem constants (fixed shapes):
//   B=128, T=2048, F_IN=32, R=256, H=256, F_OUT=32, future_n=64
//   total tokens N = 128 * (2048+64) = 270336
#define NTOTAL 270336
#define TTOT   2112
#define TIN    2048
#define NTILE  704           // 384-token tiles (24 warps x 16 tokens)
#define GRID   148

// Fused-weight fp16 images (hi only):
//   Wg: [768 gate-cols (i:0-255, g:256-511, o:512-767)][32 k]
//   dW: [32 o][256 k]
__device__ unsigned short g_WgH[768 * 32];
__device__ unsigned short g_dWH[32 * 256];
__device__ float g_bias[768];

// ---- SMEM layout (bytes). Wg rows padded to 40 halfs (80B, conflict-free
// for ldmatrix); dW stored k-chunked [4][32 o][64k pad 72]. ----
#define WG_H     0            // 768*40*2 = 61440
#define DW_H     61440        // 128*72*2 = 18432
#define BIASH2   79872        // 384 half2 (uint32) = 1536 B
#define DECB_OFF 81408        // 32 f32
#define SMEM_TOTAL 81536

__device__ __forceinline__ uint32_t smem_u32(const void* p) {
    uint32_t a;
    asm("{ .reg .u64 t; cvta.to.shared.u64 t, %1; cvt.u32.u64 %0, t; }"
        : "=r"(a) : "l"(p));
    return a;
}
__device__ __forceinline__ void ldsm4(uint32_t& r0, uint32_t& r1,
                                      uint32_t& r2, uint32_t& r3, uint32_t a) {
    asm volatile("ldmatrix.sync.aligned.m8n8.x4.shared.b16 {%0,%1,%2,%3}, [%4];"
                 : "=r"(r0), "=r"(r1), "=r"(r2), "=r"(r3) : "r"(a));
}
__device__ __forceinline__ void mma16816(float* d,
                                         uint32_t a0, uint32_t a1,
                                         uint32_t a2, uint32_t a3,
                                         uint32_t b0, uint32_t b1) {
    asm volatile(
        "mma.sync.aligned.m16n8k16.row.col.f32.f16.f16.f32 "
        "{%0,%1,%2,%3}, {%4,%5,%6,%7}, {%8,%9}, {%0,%1,%2,%3};"
        : "+f"(d[0]), "+f"(d[1]), "+f"(d[2]), "+f"(d[3])
        : "r"(a0), "r"(a1), "r"(a2), "r"(a3), "r"(b0), "r"(b1));
}
// packed half2 <-> u32
__device__ __forceinline__ uint32_t h2u(__half2 h) { uint32_t u; memcpy(&u, &h, 4); return u; }
__device__ __forceinline__ __half2  u2h(uint32_t u) { __half2 h; memcpy(&h, &u, 4); return h; }
// MUFU.TANH on packed f16x2: one MUFU op for two values
__device__ __forceinline__ __half2 tanh_h2(__half2 a) {
    uint32_t r, u = h2u(a);
    asm("tanh.approx.f16x2 %0, %1;" : "=r"(r) : "r"(u));
    return u2h(r);
}

// ---------------------------------------------------------------------------
// K1: fold encoder into LSTM input weights -> fp16 hi images.
//   bid <  768 : fused M row (one k per lane)
//   768..791   : fused biases
//   792..823   : dec_W row (o = bid-792)
// ---------------------------------------------------------------------------
__global__ void prep_kernel(const float* __restrict__ Wih,
                            const float* __restrict__ encW,
                            const float* __restrict__ encb,
                            const float* __restrict__ bih,
                            const float* __restrict__ bhh,
                            const float* __restrict__ decW) {
    __shared__ float wr_s[256];
    int bid = blockIdx.x, lane = threadIdx.x;
    if (bid < 768) {
        int p  = bid >> 8;
        int hj = bid & 255;
        int row = hj + (p == 0 ? 0 : (p == 1 ? 512 : 768));
        const float* wr = Wih + row * 256;
        #pragma unroll
        for (int i = 0; i < 8; i++) wr_s[lane + 32 * i] = wr[lane + 32 * i];
        __syncwarp();
        float s = 0.0f;
        #pragma unroll 8
        for (int r = 0; r < 256; r++) s += wr_s[r] * encW[r * 32 + lane];
        __half hi = __float2half_rn(s);
        g_WgH[bid * 32 + lane] = *(unsigned short*)&hi;
    } else if (bid < 792) {
        int q = (bid - 768) * 32 + lane;    // 0..767
        int p  = q >> 8;
        int hj = q & 255;
        int row = hj + (p == 0 ? 0 : (p == 1 ? 512 : 768));
        const float* wr = Wih + row * 256;
        float s = 0.0f;
        #pragma unroll 8
        for (int r = 0; r < 256; r++) s += wr[r] * encb[r];
        g_bias[p * 256 + hj] = s + bih[row] + bhh[row];
    } else {
        int o = bid - 792;                  // 0..31
        #pragma unroll
        for (int i = 0; i < 8; i++) {
            int k = lane + 32 * i;
            __half hi = __float2half_rn(decW[o * 256 + k]);
            g_dWH[o * 256 + k] = *(unsigned short*)&hi;
        }
    }
}

// ---------------------------------------------------------------------------
// K2: persistent fused kernel. 148 CTAs x 768 threads (24 warps), 1 CTA/SM.
// Gates: 1-term xh @ Wh (x-lo dropped; -192 MMA).  Decoder: 1-term hh @ dWh.
// Activations computed in packed f16x2: tanh.approx.f16x2 halves MUFU
// (4 MUFU per h-PAIR) and emits the decoder A-fragment directly.
// Each warp owns 16 tokens of a 384-token tile, end-to-end, no tile barriers.
// ---------------------------------------------------------------------------
__global__ __launch_bounds__(768)
void fused_kernel(const float* __restrict__ x,
                  const float* __restrict__ decb,
                  float* __restrict__ out) {
    extern __shared__ char smem[];
    int tid = threadIdx.x, wid = tid >> 5, lane = tid & 31;

    // ---- stage weights into padded smem ----
    {
        unsigned short* wgH = (unsigned short*)(smem + WG_H);
        for (int i = tid; i < 24576; i += 768) {
            int col = i >> 5, k = i & 31;
            wgH[col * 40 + k] = g_WgH[i];
        }
        unsigned short* dwH = (unsigned short*)(smem + DW_H);
        for (int i = tid; i < 8192; i += 768) {
            int o = i >> 8, k = i & 255;
            int row = (k >> 6) * 32 + o, ck = k & 63;
            dwH[row * 72 + ck] = g_dWH[i];
        }
        uint32_t* bh = (uint32_t*)(smem + BIASH2);
        for (int i = tid; i < 384; i += 768)
            bh[i] = h2u(__floats2half2_rn(g_bias[2 * i], g_bias[2 * i + 1]));
        if (tid < 32) ((float*)(smem + DECB_OFF))[tid] = decb[tid];
    }
    __syncthreads();

    uint32_t sb = smem_u32(smem);
    const uint32_t* bih2 = (const uint32_t*)(smem + BIASH2);
    const float* decb_s = (const float*)(smem + DECB_OFF);

    // ldmatrix lane geometry: j = lane/8 selects (ntile, k-half)
    int jrow = ((lane >> 4) & 1) * 8 + (lane & 7);
    int jcol = ((lane >> 3) & 1) * 8;
    int qr = lane >> 2, qc = (lane & 3) * 2;
    int m0 = wid * 16;
    const __half2 h05 = __floats2half2_rn(0.5f, 0.5f);

    for (int tile = blockIdx.x; tile < NTILE; tile += GRID) {
        int n0t  = tile * 384;
        int tok0 = n0t + m0 + qr;
        // clamped x row pointers (future steps reuse last input step)
        int b0i = tok0 / TTOT, t0 = tok0 - b0i * TTOT;
        if (t0 > TIN - 1) t0 = TIN - 1;
        int tok1 = tok0 + 8;
        int b1i = tok1 / TTOT, t1 = tok1 - b1i * TTOT;
        if (t1 > TIN - 1) t1 = TIN - 1;
        const float* xr0 = x + ((size_t)b0i * TIN + t0) * 32 + qc;
        const float* xr1 = x + ((size_t)b1i * TIN + t1) * 32 + qc;

        // A fragments for X: [kstep][a0..a3], fp16 (hi only)
        uint32_t axh[2][4];
        #pragma unroll
        for (int ks = 0; ks < 2; ks++) {
            float2 f0 = *(const float2*)(xr0 + ks * 16);
            float2 f1 = *(const float2*)(xr1 + ks * 16);
            float2 f2 = *(const float2*)(xr0 + ks * 16 + 8);
            float2 f3 = *(const float2*)(xr1 + ks * 16 + 8);
            axh[ks][0] = h2u(__floats2half2_rn(f0.x, f0.y));
            axh[ks][1] = h2u(__floats2half2_rn(f1.x, f1.y));
            axh[ks][2] = h2u(__floats2half2_rn(f2.x, f2.y));
            axh[ks][3] = h2u(__floats2half2_rn(f3.x, f3.y));
        }

        float dacc[16];
        #pragma unroll
        for (int i = 0; i < 16; i++) dacc[i] = 0.0f;

        #pragma unroll 2
        for (int c = 0; c < 8; c++) {         // 32-hj chunks
            float aI[16], aG[16], aO[16];
            #pragma unroll
            for (int i = 0; i < 16; i++) { aI[i] = 0.f; aG[i] = 0.f; aO[i] = 0.f; }

            #pragma unroll
            for (int g3 = 0; g3 < 3; g3++) {
                float* acc = (g3 == 0) ? aI : (g3 == 1 ? aG : aO);
                int colb = g3 * 256 + c * 32;
                #pragma unroll
                for (int ntp = 0; ntp < 2; ntp++) {
                    int nw = colb + ntp * 16;
                    #pragma unroll
                    for (int ks = 0; ks < 2; ks++) {
                        uint32_t adr = sb + WG_H +
                            (uint32_t)((nw + jrow) * 40 + ks * 16 + jcol) * 2;
                        uint32_t bh0, bh1, bh2, bh3;
                        ldsm4(bh0, bh1, bh2, bh3, adr);
                        float* A0 = acc + ntp * 8;
                        float* A1 = acc + ntp * 8 + 4;
                        mma16816(A0, axh[ks][0], axh[ks][1], axh[ks][2], axh[ks][3], bh0, bh1);
                        mma16816(A1, axh[ks][0], axh[ks][1], axh[ks][2], axh[ks][3], bh2, bh3);
                    }
                }
            }

            // activation in packed f16x2 -> decoder A-fragments directly.
            // h = sig(o) * tanh(sig(i) * tanh(g)), sig(v) = 0.5*tanh(0.5v)+0.5
            uint32_t hh[8];
            #pragma unroll
            for (int nt = 0; nt < 4; nt++) {
                int cb2 = c * 16 + nt * 4 + (lane & 3);   // half2 bias index
                __half2 bi = u2h(bih2[cb2]);
                __half2 bg = u2h(bih2[128 + cb2]);
                __half2 bo = u2h(bih2[256 + cb2]);
                #pragma unroll
                for (int p = 0; p < 2; p++) {
                    int q = nt * 4 + p * 2;
                    __half2 i2 = __hadd2(__floats2half2_rn(aI[q], aI[q + 1]), bi);
                    __half2 g2 = __hadd2(__floats2half2_rn(aG[q], aG[q + 1]), bg);
                    __half2 o2 = __hadd2(__floats2half2_rn(aO[q], aO[q + 1]), bo);
                    __half2 si = __hfma2(tanh_h2(__hmul2(i2, h05)), h05, h05);
                    __half2 cc = __hmul2(si, tanh_h2(g2));
                    __half2 tc = tanh_h2(cc);
                    __half2 so = __hfma2(tanh_h2(__hmul2(o2, h05)), h05, h05);
                    hh[nt * 2 + p] = h2u(__hmul2(so, tc));
                }
            }

            // decoder partial over this chunk's 32 k (h) values — hi term only
            #pragma unroll
            for (int ks = 0; ks < 2; ks++) {
                int gk = c * 32 + ks * 16;             // global k
                int kc = gk >> 6, ck = gk & 63;
                uint32_t a0h = hh[4 * ks], a1h = hh[4 * ks + 1];
                uint32_t a2h = hh[4 * ks + 2], a3h = hh[4 * ks + 3];
                #pragma unroll
                for (int otp = 0; otp < 2; otp++) {
                    uint32_t adr = sb + DW_H +
                        (uint32_t)((kc * 32 + otp * 16 + jrow) * 72 + ck + jcol) * 2;
                    uint32_t bh0, bh1, bh2, bh3;
                    ldsm4(bh0, bh1, bh2, bh3, adr);
                    float* D0 = dacc + otp * 8;
                    float* D1 = dacc + otp * 8 + 4;
                    mma16816(D0, a0h, a1h, a2h, a3h, bh0, bh1);
                    mma16816(D1, a0h, a1h, a2h, a3h, bh2, bh3);
                }
            }
        }

        // epilogue: out = dacc + dec_b
        #pragma unroll
        for (int ot = 0; ot < 4; ot++) {
            int col = ot * 8 + qc;
            float2 db = *(const float2*)&decb_s[col];
            float2 r0, r1;
            r0.x = dacc[ot * 4]     + db.x;  r0.y = dacc[ot * 4 + 1] + db.y;
            r1.x = dacc[ot * 4 + 2] + db.x;  r1.y = dacc[ot * 4 + 3] + db.y;
            *(float2*)&out[(size_t)tok0 * 32 + col]       = r0;
            *(float2*)&out[(size_t)(tok0 + 8) * 32 + col] = r1;
        }
    }
}

// ---------------------------------------------------------------------------
// Inputs (metadata order): input_seq, enc_W, enc_b, W_ih, W_hh, b_ih, b_hh,
//                          dec_W, dec_b, future_n
// W_hh is dead (state never updates from zeros); future_n fixed at 64.
// ---------------------------------------------------------------------------
extern "C" void kernel_launch(void* const* d_in, const int* in_sizes, int n_in,
                              void* d_out, int out_size) {
    (void)in_sizes; (void)n_in; (void)out_size;
    const float* input = (const float*)d_in[0];
    const float* encW  = (const float*)d_in[1];
    const float* encb  = (const float*)d_in[2];
    const float* Wih   = (const float*)d_in[3];
    const float* bih   = (const float*)d_in[5];
    const float* bhh   = (const float*)d_in[6];
    const float* decW  = (const float*)d_in[7];
    const float* decb  = (const float*)d_in[8];
    float* out = (float*)d_out;

    cudaFuncSetAttribute(fused_kernel,
                         cudaFuncAttributeMaxDynamicSharedMemorySize, SMEM_TOTAL);

    prep_kernel<<<824, 32>>>(Wih, encW, encb, bih, bhh, decW);
    fused_kernel<<<GRID, 768, SMEM_TOTAL>>>(input, decb, out);
}